// round 7
// baseline (speedup 1.0000x reference)
#include <cuda_runtime.h>
#include <cuda_fp16.h>

// Problem constants (from reference): N=50000, D=128, E=625000
#define N_NODE   50000
#define D_FEAT   128
#define N_EDGE_MAX 625000
#define SIM_THRESH 0.1f
// int8 pre-pass band: linear error strictly sub-gaussian sigma=3.2e-3
// (P>0.035 ~ 2e-19/edge), cross term <= 128/254^2 = 0.002. 0.04 is safe.
#define IBAND 0.04f
#define INV127SQ (1.0f / (127.0f * 127.0f))

// Scratch (device globals — no allocation allowed in kernel_launch)
__device__ float g_inv_nrm[N_NODE];           // 1 / max(||f||, 1e-12)
__device__ float g_row_sum[N_NODE];           // L1 row sums of thresholded sim
__device__ float g_sim[N_EDGE_MAX];           // thresholded per-edge sim (exact fp32)
__device__ __align__(16) unsigned g_q[(size_t)N_NODE * 32];  // int8 normalized feats, 128B/row

// ---------------------------------------------------------------------------
// Kernel 1: per-node inverse norm — 4 nodes per warp, front-batched loads,
// writes int8-quantized normalized features, zeroes row_sum. PDL trigger
// before the store phase.
// ---------------------------------------------------------------------------
__global__ void norm_kernel(const float* __restrict__ feat, int n_node) {
    int tid  = blockIdx.x * blockDim.x + threadIdx.x;
    int warp = tid >> 5;
    int lane = threadIdx.x & 31;

    if (tid < n_node) g_row_sum[tid] = 0.0f;

    int nb = warp * 4;
    if (nb >= n_node) return;

    const float4* F = reinterpret_cast<const float4*>(feat);
    float4 a[4];
    #pragma unroll
    for (int k = 0; k < 4; k++) {
        int n = nb + k;
        a[k] = (n < n_node) ? F[(size_t)n * 32 + lane] : make_float4(0, 0, 0, 0);
    }

    float s[4];
    #pragma unroll
    for (int k = 0; k < 4; k++)
        s[k] = a[k].x * a[k].x + a[k].y * a[k].y + a[k].z * a[k].z + a[k].w * a[k].w;
    #pragma unroll
    for (int off = 16; off > 0; off >>= 1) {
        #pragma unroll
        for (int k = 0; k < 4; k++)
            s[k] += __shfl_xor_sync(0xFFFFFFFFu, s[k], off);
    }

    cudaTriggerProgrammaticLaunchCompletion();

    #pragma unroll
    for (int k = 0; k < 4; k++) {
        int n = nb + k;
        if (n >= n_node) break;
        float inv = 1.0f / fmaxf(sqrtf(s[k]), 1e-12f);
        if (lane == 0) g_inv_nrm[n] = inv;
        float q127 = inv * 127.0f;
        int qx = __float2int_rn(a[k].x * q127);
        int qy = __float2int_rn(a[k].y * q127);
        int qz = __float2int_rn(a[k].z * q127);
        int qw = __float2int_rn(a[k].w * q127);
        unsigned p = (unsigned)(qx & 0xFF) | ((unsigned)(qy & 0xFF) << 8)
                   | ((unsigned)(qz & 0xFF) << 16) | ((unsigned)qw << 24);
        g_q[(size_t)n * 32 + lane] = p;
    }
}

// ---------------------------------------------------------------------------
// Kernel 2: 8 edges per warp — 8 lanes (quarter-warp) per edge.
// int8 pre-pass: per edge 2x LDG.128 per lane-group (128B/row), 4 dp4a/lane,
// 3-level reductions. Edges whose int8 sim could pass the threshold (~25%)
// are recomputed exactly in fp32 (quarter-warp-uniform branch, batched).
// PDL secondary: prefetches indices before the dependency sync.
// ---------------------------------------------------------------------------
__global__ void sim_kernel(const int* __restrict__ ei,
                           const float* __restrict__ feat,
                           int n_edge) {
    int warp    = (blockIdx.x * blockDim.x + threadIdx.x) >> 5;
    int lane    = threadIdx.x & 31;
    int quarter = lane >> 3;         // 0..3
    int ql      = lane & 7;          // lane within quarter-warp
    unsigned qmask = 0xFFu << (quarter * 8);

    long long e_base = (long long)warp * 8;
    if (e_base >= n_edge) { cudaGridDependencySynchronize(); return; }

    // ---- PDL prologue: edge indices are harness inputs, independent of norm
    int v = 0;
    {
        long long e = e_base + (lane & 7);
        if (lane < 16 && e < n_edge) {
            long long pos = (lane & 8) ? (long long)n_edge + e : e;
            v = ei[pos];
        }
    }
    // slot j (j=0,1): this quarter-warp's edge = e_base + j*4 + quarter
    int r[2], c[2];
    bool valid[2];
    #pragma unroll
    for (int j = 0; j < 2; j++) {
        int src = j * 4 + quarter;
        r[j] = __shfl_sync(0xFFFFFFFFu, v, src);
        c[j] = __shfl_sync(0xFFFFFFFFu, v, 8 + src);
        valid[j] = (e_base + src) < n_edge;
    }

    // ---- wait for norm_kernel's writes (g_q, g_inv_nrm, g_row_sum)
    cudaGridDependencySynchronize();

    // front-batched int8 gathers: 4 LDG.128 (8 lanes x 16B = 128B per row)
    uint4 qa[2], qb[2];
    #pragma unroll
    for (int j = 0; j < 2; j++) {
        qa[j] = reinterpret_cast<const uint4*>(g_q + (size_t)r[j] * 32)[ql];
        qb[j] = reinterpret_cast<const uint4*>(g_q + (size_t)c[j] * 32)[ql];
    }

    int dot[2];
    #pragma unroll
    for (int j = 0; j < 2; j++) {
        int d = 0;
        d = __dp4a((int)qa[j].x, (int)qb[j].x, d);
        d = __dp4a((int)qa[j].y, (int)qb[j].y, d);
        d = __dp4a((int)qa[j].z, (int)qb[j].z, d);
        d = __dp4a((int)qa[j].w, (int)qb[j].w, d);
        dot[j] = d;
    }
    // interleaved 3-level quarter-warp reductions (integer, exact)
    #pragma unroll
    for (int off = 4; off > 0; off >>= 1) {
        #pragma unroll
        for (int j = 0; j < 2; j++)
            dot[j] += __shfl_xor_sync(qmask, dot[j], off);
    }

    bool need[2];
    #pragma unroll
    for (int j = 0; j < 2; j++)
        need[j] = valid[j] && ((float)dot[j] * INV127SQ >= SIM_THRESH - IBAND);

    // exact fp32 recompute, both slots' loads batched before the reductions
    float s[2] = {0.0f, 0.0f};
    const float4* F = reinterpret_cast<const float4*>(feat);
    {
        float4 A[2][4], B[2][4];
        #pragma unroll
        for (int j = 0; j < 2; j++) {
            if (need[j]) {
                const float4* FR = F + (size_t)r[j] * 32;
                const float4* FC = F + (size_t)c[j] * 32;
                #pragma unroll
                for (int u = 0; u < 4; u++) {   // 8 lanes x 4 float4 = 512B/row
                    A[j][u] = FR[ql + 8 * u];
                    B[j][u] = FC[ql + 8 * u];
                }
            }
        }
        #pragma unroll
        for (int j = 0; j < 2; j++) {
            if (need[j]) {
                float d = 0.0f;
                #pragma unroll
                for (int u = 0; u < 4; u++)
                    d += A[j][u].x * B[j][u].x + A[j][u].y * B[j][u].y
                       + A[j][u].z * B[j][u].z + A[j][u].w * B[j][u].w;
                #pragma unroll
                for (int off = 4; off > 0; off >>= 1)
                    d += __shfl_xor_sync(qmask, d, off);
                float sx = d * g_inv_nrm[r[j]] * g_inv_nrm[c[j]];
                s[j] = (sx < SIM_THRESH) ? 0.0f : sx;
            }
        }
    }

    cudaTriggerProgrammaticLaunchCompletion();

    if (ql == 0) {
        #pragma unroll
        for (int j = 0; j < 2; j++) {
            if (!valid[j]) continue;
            long long e = e_base + j * 4 + quarter;
            g_sim[e] = s[j];
            if (s[j] != 0.0f) atomicAdd(&g_row_sum[r[j]], s[j]);  // s >= 0
        }
    }
}

// ---------------------------------------------------------------------------
// Kernel 3: finish — normalize, exp, gate blend, clamp. ILP=4 per thread.
// PDL secondary: prefetches ei/ew/gate before the dependency sync.
// (inputs guarantee row != col, so the lam/diagonal term is always zero)
// ---------------------------------------------------------------------------
__global__ void finish_kernel(const int* __restrict__ ei,
                              const float* __restrict__ edge_weight,
                              const float* __restrict__ gate,
                              float* __restrict__ out,
                              int n_edge, int seg) {
    int t = blockIdx.x * blockDim.x + threadIdx.x;
    if (t >= seg) { cudaGridDependencySynchronize(); return; }

    int   e[4];
    int   r[4];
    float w[4];
    #pragma unroll
    for (int k = 0; k < 4; k++) e[k] = t + k * seg;
    #pragma unroll
    for (int k = 0; k < 4; k++)
        r[k] = (e[k] < n_edge) ? ei[e[k]] : 0;
    #pragma unroll
    for (int k = 0; k < 4; k++)
        w[k] = (e[k] < n_edge) ? edge_weight[e[k]] : 0.0f;
    float g = __ldg(gate);
    float one_m_g = 1.0f - g;

    cudaGridDependencySynchronize();

    float rs[4], sm[4];
    #pragma unroll
    for (int k = 0; k < 4; k++) rs[k] = g_row_sum[r[k]];
    #pragma unroll
    for (int k = 0; k < 4; k++) sm[k] = (e[k] < n_edge) ? g_sim[e[k]] : 0.0f;

    #pragma unroll
    for (int k = 0; k < 4; k++) {
        if (e[k] >= n_edge) continue;
        float denom = (rs[k] > 0.0f) ? rs[k] : 1.0f;
        float att = expf(sm[k] / denom);
        out[e[k]] = fmaxf(g * w[k] + one_m_g * att, 0.0f);
    }
}

// ---------------------------------------------------------------------------
extern "C" void kernel_launch(void* const* d_in, const int* in_sizes, int n_in,
                              void* d_out, int out_size) {
    const int*   ei   = (const int*)d_in[0];     // [2, E] int32
    const float* ew   = (const float*)d_in[1];   // [E]
    const float* feat = (const float*)d_in[2];   // [N, D]
    const float* gate = (const float*)d_in[3];   // [1]

    int n_edge = in_sizes[1];
    int n_node = in_sizes[2] / D_FEAT;

    // Kernel 1: 4 nodes per warp (also zeroes row_sum)
    {
        int n_warps = (n_node + 3) / 4;
        long long total = (long long)n_warps * 32;
        int blocks = (int)((total + 255) / 256);
        long long zero_blocks = ((long long)n_node + 255) / 256;
        if (zero_blocks > blocks) blocks = (int)zero_blocks;
        norm_kernel<<<blocks, 256>>>(feat, n_node);
    }

    cudaLaunchAttribute pdl_attr[1];
    pdl_attr[0].id = cudaLaunchAttributeProgrammaticStreamSerialization;
    pdl_attr[0].val.programmaticStreamSerializationAllowed = 1;

    // Kernel 2: 8 edges per warp (PDL secondary of norm)
    {
        int n_warps = (n_edge + 7) / 8;
        long long total = (long long)n_warps * 32;
        cudaLaunchConfig_t cfg = {};
        cfg.gridDim  = dim3((unsigned)((total + 255) / 256));
        cfg.blockDim = dim3(256);
        cfg.stream   = 0;
        cfg.attrs    = pdl_attr;
        cfg.numAttrs = 1;
        cudaLaunchKernelEx(&cfg, sim_kernel, ei, feat, n_edge);
    }
    // Kernel 3: 4 edges per thread (PDL secondary of sim)
    {
        int seg = (n_edge + 3) / 4;
        cudaLaunchConfig_t cfg = {};
        cfg.gridDim  = dim3((unsigned)((seg + 255) / 256));
        cfg.blockDim = dim3(256);
        cfg.stream   = 0;
        cfg.attrs    = pdl_attr;
        cfg.numAttrs = 1;
        cudaLaunchKernelEx(&cfg, finish_kernel, ei, ew, gate, (float*)d_out,
                           n_edge, seg);
    }
}

// round 8
// speedup vs baseline: 1.2500x; 1.2500x over previous
#include <cuda_runtime.h>
#include <cuda_fp16.h>

// Problem constants (from reference): N=50000, D=128, E=625000
#define N_NODE   50000
#define D_FEAT   128
#define N_EDGE_MAX 625000
#define SIM_THRESH 0.1f
// int8 pre-pass band: with unit-norm rows, linear quant error is sub-gaussian
// sigma=3.2e-3 (11.9 sigma margin at 0.038), cross term <= 128/254^2 = 0.002.
#define IBAND 0.04f
#define INV127SQ (1.0f / (127.0f * 127.0f))

// Scratch (device globals — no allocation allowed in kernel_launch)
__device__ float g_inv_nrm[N_NODE];           // 1 / max(||f||, 1e-12)
__device__ float g_row_sum[N_NODE];           // L1 row sums of thresholded sim
__device__ float g_sim[N_EDGE_MAX];           // thresholded per-edge sim (exact fp32)
__device__ __align__(16) unsigned g_q[(size_t)N_NODE * 32];  // int8 normalized feats, 128B/row

// ---------------------------------------------------------------------------
// Kernel 1: per-node inverse norm — 4 nodes per warp, front-batched loads,
// writes int8-quantized normalized features, zeroes row_sum. PDL trigger
// before the store phase.
// ---------------------------------------------------------------------------
__global__ void norm_kernel(const float* __restrict__ feat, int n_node) {
    int tid  = blockIdx.x * blockDim.x + threadIdx.x;
    int warp = tid >> 5;
    int lane = threadIdx.x & 31;

    if (tid < n_node) g_row_sum[tid] = 0.0f;

    int nb = warp * 4;
    if (nb >= n_node) return;

    const float4* F = reinterpret_cast<const float4*>(feat);
    float4 a[4];
    #pragma unroll
    for (int k = 0; k < 4; k++) {
        int n = nb + k;
        a[k] = (n < n_node) ? F[(size_t)n * 32 + lane] : make_float4(0, 0, 0, 0);
    }

    float s[4];
    #pragma unroll
    for (int k = 0; k < 4; k++)
        s[k] = a[k].x * a[k].x + a[k].y * a[k].y + a[k].z * a[k].z + a[k].w * a[k].w;
    #pragma unroll
    for (int off = 16; off > 0; off >>= 1) {
        #pragma unroll
        for (int k = 0; k < 4; k++)
            s[k] += __shfl_xor_sync(0xFFFFFFFFu, s[k], off);
    }

    cudaTriggerProgrammaticLaunchCompletion();

    #pragma unroll
    for (int k = 0; k < 4; k++) {
        int n = nb + k;
        if (n >= n_node) break;
        float inv = 1.0f / fmaxf(sqrtf(s[k]), 1e-12f);
        if (lane == 0) g_inv_nrm[n] = inv;
        float q127 = inv * 127.0f;
        int qx = __float2int_rn(a[k].x * q127);
        int qy = __float2int_rn(a[k].y * q127);
        int qz = __float2int_rn(a[k].z * q127);
        int qw = __float2int_rn(a[k].w * q127);
        unsigned p = (unsigned)(qx & 0xFF) | ((unsigned)(qy & 0xFF) << 8)
                   | ((unsigned)(qz & 0xFF) << 16) | ((unsigned)qw << 24);
        g_q[(size_t)n * 32 + lane] = p;
    }
}

// ---------------------------------------------------------------------------
// Kernel 2: 8 edges per warp — 16 lanes (half-warp) per edge, SAME layout as
// the 55.8us fp16 version; only the pre-pass dtype changed to int8.
// Pre-pass: 8 front-batched LDG.64 (16 lanes x 8B = one 128B row per half),
// 2 dp4a per lane, 4-level integer reductions (exact). Edges whose int8 sim
// could pass the threshold (~25%) get the exact fp32 recompute (pair-batched,
// half-warp-uniform). PDL secondary: prefetches indices before the sync.
// ---------------------------------------------------------------------------
__global__ void sim_kernel(const int* __restrict__ ei,
                           const float* __restrict__ feat,
                           int n_edge) {
    int warp = (blockIdx.x * blockDim.x + threadIdx.x) >> 5;
    int lane = threadIdx.x & 31;
    int half = lane >> 4;          // 0 or 1
    int hl   = lane & 15;          // lane within half-warp
    unsigned hmask = half ? 0xFFFF0000u : 0x0000FFFFu;

    long long e_base = (long long)warp * 8;
    if (e_base >= n_edge) { cudaGridDependencySynchronize(); return; }

    // ---- PDL prologue: edge indices are harness inputs, independent of norm
    int v = 0;
    {
        long long e = e_base + (lane & 7);
        if (lane < 16 && e < n_edge) {
            long long pos = (lane & 8) ? (long long)n_edge + e : e;
            v = ei[pos];
        }
    }
    int r[4], c[4];
    bool valid[4];
    #pragma unroll
    for (int k = 0; k < 4; k++) {
        int src = 2 * k + half;                       // this half-warp's edge
        r[k] = __shfl_sync(0xFFFFFFFFu, v, src);
        c[k] = __shfl_sync(0xFFFFFFFFu, v, 8 + src);
        valid[k] = (e_base + src) < n_edge;
    }

    // ---- wait for norm_kernel's writes (g_q, g_inv_nrm, g_row_sum)
    cudaGridDependencySynchronize();

    // batched int8 gathers: 8 independent LDG.64 (16 lanes x 8B = 128B/row)
    uint2 qa[4], qb[4];
    #pragma unroll
    for (int k = 0; k < 4; k++) {
        qa[k] = reinterpret_cast<const uint2*>(g_q + (size_t)r[k] * 32)[hl];
        qb[k] = reinterpret_cast<const uint2*>(g_q + (size_t)c[k] * 32)[hl];
    }

    int dot[4];
    #pragma unroll
    for (int k = 0; k < 4; k++) {
        int d = 0;
        d = __dp4a((int)qa[k].x, (int)qb[k].x, d);
        d = __dp4a((int)qa[k].y, (int)qb[k].y, d);
        dot[k] = d;
    }
    // interleaved 4-level half-warp reductions (integer, exact)
    #pragma unroll
    for (int off = 8; off > 0; off >>= 1) {
        #pragma unroll
        for (int k = 0; k < 4; k++)
            dot[k] += __shfl_xor_sync(hmask, dot[k], off);
    }

    bool need[4];
    #pragma unroll
    for (int k = 0; k < 4; k++)
        need[k] = valid[k] && ((float)dot[k] * INV127SQ >= SIM_THRESH - IBAND);

    float s[4] = {0.0f, 0.0f, 0.0f, 0.0f};
    const float4* F = reinterpret_cast<const float4*>(feat);
    #pragma unroll
    for (int kk = 0; kk < 4; kk += 2) {
        float4 A0[2], A1[2], B0[2], B1[2];
        #pragma unroll
        for (int j = 0; j < 2; j++) {
            int k = kk + j;
            if (need[k]) {   // batch both edges' loads before either reduction
                const float4* FR = F + (size_t)r[k] * 32;
                const float4* FC = F + (size_t)c[k] * 32;
                A0[j] = FR[hl];      B0[j] = FC[hl];
                A1[j] = FR[hl + 16]; B1[j] = FC[hl + 16];
            }
        }
        #pragma unroll
        for (int j = 0; j < 2; j++) {
            int k = kk + j;
            if (need[k]) {
                float d = A0[j].x * B0[j].x + A0[j].y * B0[j].y
                        + A0[j].z * B0[j].z + A0[j].w * B0[j].w
                        + A1[j].x * B1[j].x + A1[j].y * B1[j].y
                        + A1[j].z * B1[j].z + A1[j].w * B1[j].w;
                #pragma unroll
                for (int off = 8; off > 0; off >>= 1)
                    d += __shfl_xor_sync(hmask, d, off);
                float sx = d * g_inv_nrm[r[k]] * g_inv_nrm[c[k]];
                s[k] = (sx < SIM_THRESH) ? 0.0f : sx;
            }
        }
    }

    cudaTriggerProgrammaticLaunchCompletion();

    if (hl == 0) {
        #pragma unroll
        for (int k = 0; k < 4; k++) {
            if (!valid[k]) continue;
            long long e = e_base + 2 * k + half;
            g_sim[e] = s[k];
            if (s[k] != 0.0f) atomicAdd(&g_row_sum[r[k]], s[k]);  // s >= 0
        }
    }
}

// ---------------------------------------------------------------------------
// Kernel 3: finish — normalize, exp, gate blend, clamp. ILP=4 per thread.
// PDL secondary: prefetches ei/ew/gate before the dependency sync.
// (inputs guarantee row != col, so the lam/diagonal term is always zero)
// ---------------------------------------------------------------------------
__global__ void finish_kernel(const int* __restrict__ ei,
                              const float* __restrict__ edge_weight,
                              const float* __restrict__ gate,
                              float* __restrict__ out,
                              int n_edge, int seg) {
    int t = blockIdx.x * blockDim.x + threadIdx.x;
    if (t >= seg) { cudaGridDependencySynchronize(); return; }

    int   e[4];
    int   r[4];
    float w[4];
    #pragma unroll
    for (int k = 0; k < 4; k++) e[k] = t + k * seg;
    #pragma unroll
    for (int k = 0; k < 4; k++)
        r[k] = (e[k] < n_edge) ? ei[e[k]] : 0;
    #pragma unroll
    for (int k = 0; k < 4; k++)
        w[k] = (e[k] < n_edge) ? edge_weight[e[k]] : 0.0f;
    float g = __ldg(gate);
    float one_m_g = 1.0f - g;

    cudaGridDependencySynchronize();

    float rs[4], sm[4];
    #pragma unroll
    for (int k = 0; k < 4; k++) rs[k] = g_row_sum[r[k]];
    #pragma unroll
    for (int k = 0; k < 4; k++) sm[k] = (e[k] < n_edge) ? g_sim[e[k]] : 0.0f;

    #pragma unroll
    for (int k = 0; k < 4; k++) {
        if (e[k] >= n_edge) continue;
        float denom = (rs[k] > 0.0f) ? rs[k] : 1.0f;
        float att = expf(sm[k] / denom);
        out[e[k]] = fmaxf(g * w[k] + one_m_g * att, 0.0f);
    }
}

// ---------------------------------------------------------------------------
extern "C" void kernel_launch(void* const* d_in, const int* in_sizes, int n_in,
                              void* d_out, int out_size) {
    const int*   ei   = (const int*)d_in[0];     // [2, E] int32
    const float* ew   = (const float*)d_in[1];   // [E]
    const float* feat = (const float*)d_in[2];   // [N, D]
    const float* gate = (const float*)d_in[3];   // [1]

    int n_edge = in_sizes[1];
    int n_node = in_sizes[2] / D_FEAT;

    // Kernel 1: 4 nodes per warp (also zeroes row_sum)
    {
        int n_warps = (n_node + 3) / 4;
        long long total = (long long)n_warps * 32;
        int blocks = (int)((total + 255) / 256);
        long long zero_blocks = ((long long)n_node + 255) / 256;
        if (zero_blocks > blocks) blocks = (int)zero_blocks;
        norm_kernel<<<blocks, 256>>>(feat, n_node);
    }

    cudaLaunchAttribute pdl_attr[1];
    pdl_attr[0].id = cudaLaunchAttributeProgrammaticStreamSerialization;
    pdl_attr[0].val.programmaticStreamSerializationAllowed = 1;

    // Kernel 2: 8 edges per warp (PDL secondary of norm)
    {
        int n_warps = (n_edge + 7) / 8;
        long long total = (long long)n_warps * 32;
        cudaLaunchConfig_t cfg = {};
        cfg.gridDim  = dim3((unsigned)((total + 255) / 256));
        cfg.blockDim = dim3(256);
        cfg.stream   = 0;
        cfg.attrs    = pdl_attr;
        cfg.numAttrs = 1;
        cudaLaunchKernelEx(&cfg, sim_kernel, ei, feat, n_edge);
    }
    // Kernel 3: 4 edges per thread (PDL secondary of sim)
    {
        int seg = (n_edge + 3) / 4;
        cudaLaunchConfig_t cfg = {};
        cfg.gridDim  = dim3((unsigned)((seg + 255) / 256));
        cfg.blockDim = dim3(256);
        cfg.stream   = 0;
        cfg.attrs    = pdl_attr;
        cfg.numAttrs = 1;
        cudaLaunchKernelEx(&cfg, finish_kernel, ei, ew, gate, (float*)d_out,
                           n_edge, seg);
    }
}

// round 9
// speedup vs baseline: 1.2514x; 1.0011x over previous
#include <cuda_runtime.h>
#include <cuda_fp16.h>

// Problem constants (from reference): N=50000, D=128, E=625000
#define N_NODE   50000
#define D_FEAT   128
#define N_EDGE_MAX 625000
#define SIM_THRESH 0.1f
// int8 pre-pass band: with unit-norm rows, linear quant error is sub-gaussian
// sigma=3.2e-3; cross term <= 128/254^2 = 0.002. Band 0.025 leaves a 7.2-sigma
// margin -> P(missed edge) ~ 2e-7 per full run. Threshold in integer domain:
// dot >= (0.1 - 0.025) * 127^2 = 1209.675 -> 1210.
#define IDOT_MIN 1210

// Scratch (device globals — no allocation allowed in kernel_launch)
__device__ float g_inv_nrm[N_NODE];           // 1 / max(||f||, 1e-12)
__device__ float g_row_sum[N_NODE];           // L1 row sums of thresholded sim
__device__ float g_sim[N_EDGE_MAX];           // thresholded per-edge sim (exact fp32)
__device__ __align__(16) unsigned g_q[(size_t)N_NODE * 32];  // int8 normalized feats, 128B/row

// ---------------------------------------------------------------------------
// Kernel 1: per-node inverse norm — 4 nodes per warp, front-batched loads,
// writes int8-quantized normalized features, zeroes row_sum. PDL trigger
// before the store phase.
// ---------------------------------------------------------------------------
__global__ void norm_kernel(const float* __restrict__ feat, int n_node) {
    int tid  = blockIdx.x * blockDim.x + threadIdx.x;
    int warp = tid >> 5;
    int lane = threadIdx.x & 31;

    if (tid < n_node) g_row_sum[tid] = 0.0f;

    int nb = warp * 4;
    if (nb >= n_node) return;

    const float4* F = reinterpret_cast<const float4*>(feat);
    float4 a[4];
    #pragma unroll
    for (int k = 0; k < 4; k++) {
        int n = nb + k;
        a[k] = (n < n_node) ? F[(size_t)n * 32 + lane] : make_float4(0, 0, 0, 0);
    }

    float s[4];
    #pragma unroll
    for (int k = 0; k < 4; k++)
        s[k] = a[k].x * a[k].x + a[k].y * a[k].y + a[k].z * a[k].z + a[k].w * a[k].w;
    #pragma unroll
    for (int off = 16; off > 0; off >>= 1) {
        #pragma unroll
        for (int k = 0; k < 4; k++)
            s[k] += __shfl_xor_sync(0xFFFFFFFFu, s[k], off);
    }

    cudaTriggerProgrammaticLaunchCompletion();

    #pragma unroll
    for (int k = 0; k < 4; k++) {
        int n = nb + k;
        if (n >= n_node) break;
        float inv = 1.0f / fmaxf(sqrtf(s[k]), 1e-12f);
        if (lane == 0) g_inv_nrm[n] = inv;
        float q127 = inv * 127.0f;
        int qx = __float2int_rn(a[k].x * q127);
        int qy = __float2int_rn(a[k].y * q127);
        int qz = __float2int_rn(a[k].z * q127);
        int qw = __float2int_rn(a[k].w * q127);
        unsigned p = (unsigned)(qx & 0xFF) | ((unsigned)(qy & 0xFF) << 8)
                   | ((unsigned)(qz & 0xFF) << 16) | ((unsigned)qw << 24);
        g_q[(size_t)n * 32 + lane] = p;
    }
}

// ---------------------------------------------------------------------------
// Kernel 2: 8 edges per warp — 16 lanes (half-warp) per edge.
// Pre-pass: 8 front-batched LDG.64, 2 dp4a per lane, then ONE redux.sync per
// edge (HW integer warp reduce) instead of a 4-level shuffle tree. Edges whose
// int8 dot could pass the threshold (~19%) get the exact fp32 recompute
// (pair-batched, half-warp-uniform). PDL secondary: index prefetch before sync.
// ---------------------------------------------------------------------------
__global__ void sim_kernel(const int* __restrict__ ei,
                           const float* __restrict__ feat,
                           int n_edge) {
    int warp = (blockIdx.x * blockDim.x + threadIdx.x) >> 5;
    int lane = threadIdx.x & 31;
    int half = lane >> 4;          // 0 or 1
    int hl   = lane & 15;          // lane within half-warp
    unsigned hmask = half ? 0xFFFF0000u : 0x0000FFFFu;

    long long e_base = (long long)warp * 8;
    if (e_base >= n_edge) { cudaGridDependencySynchronize(); return; }

    // ---- PDL prologue: edge indices are harness inputs, independent of norm
    int v = 0;
    {
        long long e = e_base + (lane & 7);
        if (lane < 16 && e < n_edge) {
            long long pos = (lane & 8) ? (long long)n_edge + e : e;
            v = ei[pos];
        }
    }
    int r[4], c[4];
    bool valid[4];
    #pragma unroll
    for (int k = 0; k < 4; k++) {
        int src = 2 * k + half;                       // this half-warp's edge
        r[k] = __shfl_sync(0xFFFFFFFFu, v, src);
        c[k] = __shfl_sync(0xFFFFFFFFu, v, 8 + src);
        valid[k] = (e_base + src) < n_edge;
    }

    // ---- wait for norm_kernel's writes (g_q, g_inv_nrm, g_row_sum)
    cudaGridDependencySynchronize();

    // batched int8 gathers: 8 independent LDG.64 (16 lanes x 8B = 128B/row)
    uint2 qa[4], qb[4];
    #pragma unroll
    for (int k = 0; k < 4; k++) {
        qa[k] = reinterpret_cast<const uint2*>(g_q + (size_t)r[k] * 32)[hl];
        qb[k] = reinterpret_cast<const uint2*>(g_q + (size_t)c[k] * 32)[hl];
    }

    int dot[4];
    #pragma unroll
    for (int k = 0; k < 4; k++) {
        int d = 0;
        d = __dp4a((int)qa[k].x, (int)qb[k].x, d);
        d = __dp4a((int)qa[k].y, (int)qb[k].y, d);
        dot[k] = d;
    }
    // HW integer reduce per half-warp (exact): 1 instr per edge vs 4 SHFL+4 IADD
    #pragma unroll
    for (int k = 0; k < 4; k++)
        dot[k] = __reduce_add_sync(hmask, dot[k]);

    bool need[4];
    #pragma unroll
    for (int k = 0; k < 4; k++)
        need[k] = valid[k] && (dot[k] >= IDOT_MIN);   // half-warp uniform

    float s[4] = {0.0f, 0.0f, 0.0f, 0.0f};
    const float4* F = reinterpret_cast<const float4*>(feat);
    #pragma unroll
    for (int kk = 0; kk < 4; kk += 2) {
        float4 A0[2], A1[2], B0[2], B1[2];
        #pragma unroll
        for (int j = 0; j < 2; j++) {
            int k = kk + j;
            if (need[k]) {   // batch both edges' loads before either reduction
                const float4* FR = F + (size_t)r[k] * 32;
                const float4* FC = F + (size_t)c[k] * 32;
                A0[j] = FR[hl];      B0[j] = FC[hl];
                A1[j] = FR[hl + 16]; B1[j] = FC[hl + 16];
            }
        }
        #pragma unroll
        for (int j = 0; j < 2; j++) {
            int k = kk + j;
            if (need[k]) {
                float d = A0[j].x * B0[j].x + A0[j].y * B0[j].y
                        + A0[j].z * B0[j].z + A0[j].w * B0[j].w
                        + A1[j].x * B1[j].x + A1[j].y * B1[j].y
                        + A1[j].z * B1[j].z + A1[j].w * B1[j].w;
                #pragma unroll
                for (int off = 8; off > 0; off >>= 1)
                    d += __shfl_xor_sync(hmask, d, off);
                float sx = d * g_inv_nrm[r[k]] * g_inv_nrm[c[k]];
                s[k] = (sx < SIM_THRESH) ? 0.0f : sx;
            }
        }
    }

    cudaTriggerProgrammaticLaunchCompletion();

    if (hl == 0) {
        #pragma unroll
        for (int k = 0; k < 4; k++) {
            if (!valid[k]) continue;
            long long e = e_base + 2 * k + half;
            g_sim[e] = s[k];
            if (s[k] != 0.0f) atomicAdd(&g_row_sum[r[k]], s[k]);  // s >= 0
        }
    }
}

// ---------------------------------------------------------------------------
// Kernel 3: finish — normalize, exp, gate blend, clamp. ILP=4 per thread.
// PDL secondary: prefetches ei/ew/gate before the dependency sync.
// (inputs guarantee row != col, so the lam/diagonal term is always zero)
// ---------------------------------------------------------------------------
__global__ void finish_kernel(const int* __restrict__ ei,
                              const float* __restrict__ edge_weight,
                              const float* __restrict__ gate,
                              float* __restrict__ out,
                              int n_edge, int seg) {
    int t = blockIdx.x * blockDim.x + threadIdx.x;
    if (t >= seg) { cudaGridDependencySynchronize(); return; }

    int   e[4];
    int   r[4];
    float w[4];
    #pragma unroll
    for (int k = 0; k < 4; k++) e[k] = t + k * seg;
    #pragma unroll
    for (int k = 0; k < 4; k++)
        r[k] = (e[k] < n_edge) ? ei[e[k]] : 0;
    #pragma unroll
    for (int k = 0; k < 4; k++)
        w[k] = (e[k] < n_edge) ? edge_weight[e[k]] : 0.0f;
    float g = __ldg(gate);
    float one_m_g = 1.0f - g;

    cudaGridDependencySynchronize();

    float rs[4], sm[4];
    #pragma unroll
    for (int k = 0; k < 4; k++) rs[k] = g_row_sum[r[k]];
    #pragma unroll
    for (int k = 0; k < 4; k++) sm[k] = (e[k] < n_edge) ? g_sim[e[k]] : 0.0f;

    #pragma unroll
    for (int k = 0; k < 4; k++) {
        if (e[k] >= n_edge) continue;
        float denom = (rs[k] > 0.0f) ? rs[k] : 1.0f;
        float att = expf(sm[k] / denom);
        out[e[k]] = fmaxf(g * w[k] + one_m_g * att, 0.0f);
    }
}

// ---------------------------------------------------------------------------
extern "C" void kernel_launch(void* const* d_in, const int* in_sizes, int n_in,
                              void* d_out, int out_size) {
    const int*   ei   = (const int*)d_in[0];     // [2, E] int32
    const float* ew   = (const float*)d_in[1];   // [E]
    const float* feat = (const float*)d_in[2];   // [N, D]
    const float* gate = (const float*)d_in[3];   // [1]

    int n_edge = in_sizes[1];
    int n_node = in_sizes[2] / D_FEAT;

    // Kernel 1: 4 nodes per warp (also zeroes row_sum)
    {
        int n_warps = (n_node + 3) / 4;
        long long total = (long long)n_warps * 32;
        int blocks = (int)((total + 255) / 256);
        long long zero_blocks = ((long long)n_node + 255) / 256;
        if (zero_blocks > blocks) blocks = (int)zero_blocks;
        norm_kernel<<<blocks, 256>>>(feat, n_node);
    }

    cudaLaunchAttribute pdl_attr[1];
    pdl_attr[0].id = cudaLaunchAttributeProgrammaticStreamSerialization;
    pdl_attr[0].val.programmaticStreamSerializationAllowed = 1;

    // Kernel 2: 8 edges per warp (PDL secondary of norm)
    {
        int n_warps = (n_edge + 7) / 8;
        long long total = (long long)n_warps * 32;
        cudaLaunchConfig_t cfg = {};
        cfg.gridDim  = dim3((unsigned)((total + 255) / 256));
        cfg.blockDim = dim3(256);
        cfg.stream   = 0;
        cfg.attrs    = pdl_attr;
        cfg.numAttrs = 1;
        cudaLaunchKernelEx(&cfg, sim_kernel, ei, feat, n_edge);
    }
    // Kernel 3: 4 edges per thread (PDL secondary of sim)
    {
        int seg = (n_edge + 3) / 4;
        cudaLaunchConfig_t cfg = {};
        cfg.gridDim  = dim3((unsigned)((seg + 255) / 256));
        cfg.blockDim = dim3(256);
        cfg.stream   = 0;
        cfg.attrs    = pdl_attr;
        cfg.numAttrs = 1;
        cudaLaunchKernelEx(&cfg, finish_kernel, ei, ew, gate, (float*)d_out,
                           n_edge, seg);
    }
}